// round 5
// baseline (speedup 1.0000x reference)
#include <cuda_runtime.h>
#include <cuda_bf16.h>
#include <cuda_fp16.h>
#include <math.h>
#include <float.h>
#include <stdint.h>

// Problem constants
#define NB   2
#define CC   128
#define HH   64
#define WW   64
#define HS   128
#define WS   128
#define HP   62          // HH - 2
#define USZ  126         // HS - 2
#define M_R  4096        // HH*WW   (ref pixels per image)
#define N_S  16384       // HS*WS   (shape pixels per image)

// Scratch
static __device__ uint8_t  g_Tf8[(size_t)NB * M_R * N_S];        // 134 MB e4m3 Gram matrix
static __device__ uint32_t g_Apk[(size_t)NB * (CC/2) * M_R];     // 2 MB  bf162 k-pair packed ref
static __device__ uint32_t g_Bpk[(size_t)NB * (CC/2) * N_S];     // 8 MB  bf162 k-pair packed shape
static __device__ int      g_idx[NB * HP * HP];

// ---------------------------------------------------------------------------
// Kernel 0: zero the output scalar(s)
// ---------------------------------------------------------------------------
__global__ void zero_kernel(float* out, int n) {
    for (int i = threadIdx.x; i < n; i += blockDim.x) out[i] = 0.0f;
}

// ---------------------------------------------------------------------------
// Kernel 0b: pack fp32 [n][c][m] -> bf162 k-pair layout [n][k2][m]
// ---------------------------------------------------------------------------
__global__ void pack_kernel(const float* __restrict__ src, uint32_t* __restrict__ dst,
                            int M, int total) {
    for (int x = blockIdx.x * blockDim.x + threadIdx.x; x < total;
         x += gridDim.x * blockDim.x) {
        int m   = x % M;
        int nk2 = x / M;
        int n   = nk2 >> 6;       // /64
        int k2  = nk2 & 63;
        const float* s = src + ((size_t)(n * CC + 2 * k2)) * M + m;
        __nv_bfloat162 h = __floats2bfloat162_rn(s[0], s[M]);
        dst[x] = *(uint32_t*)&h;
    }
}

// ---------------------------------------------------------------------------
// Kernel 1: T[n,r,s] = sum_c ref[n,c,r] * shape[n,c,s]   (bf16 HMMA, f32 acc)
// Double-buffered cp.async, 128x128 tile, epilogue converts to e4m3.
// ---------------------------------------------------------------------------
#define BM 128
#define BN 128
#define BK2 16          // k-pair rows per stage (BK = 32)
#define SPITCH 132      // padded row stride in u32

__device__ __forceinline__ void cp_async16(uint32_t smem_addr, const void* gptr) {
    asm volatile("cp.async.cg.shared.global [%0], [%1], 16;\n"
                 :: "r"(smem_addr), "l"(gptr));
}

__device__ __forceinline__ uint16_t f32x2_to_e4m3x2(float hi, float lo) {
    uint16_t w;
    asm("cvt.rn.satfinite.e4m3x2.f32 %0, %1, %2;" : "=h"(w) : "f"(hi), "f"(lo));
    return w;   // low byte = lo, high byte = hi
}

__global__ __launch_bounds__(256) void gemm_kernel() {
    __shared__ __align__(16) uint32_t As2[2][BK2 * SPITCH];
    __shared__ __align__(16) uint32_t Bs2[2][BK2 * SPITCH];

    const int n = blockIdx.z;
    const uint32_t* Ap = g_Apk + (size_t)n * (CC / 2) * M_R;
    const uint32_t* Bp = g_Bpk + (size_t)n * (CC / 2) * N_S;
    uint8_t*        Ct = g_Tf8 + (size_t)n * M_R * N_S;

    const int r0 = blockIdx.y * BM;
    const int s0 = blockIdx.x * BN;
    const int tid  = threadIdx.x;
    const int lane = tid & 31;
    const int wid  = tid >> 5;
    const int warp_m = (wid >> 2) * 64;
    const int warp_n = (wid & 3) * 32;
    const int g    = lane >> 2;
    const int tid4 = lane & 3;

    const uint32_t sA = (uint32_t)__cvta_generic_to_shared(&As2[0][0]);
    const uint32_t sB = (uint32_t)__cvta_generic_to_shared(&Bs2[0][0]);

    auto issue = [&](int buf, int kk2) {
#pragma unroll
        for (int h = 0; h < 2; h++) {
            int ch = tid + h * 256;
            int k2 = ch >> 5;
            int m4 = (ch & 31) << 2;
            uint32_t doff = (uint32_t)((buf * BK2 * SPITCH + k2 * SPITCH + m4) * 4);
            cp_async16(sA + doff, Ap + (size_t)(kk2 + k2) * M_R + r0 + m4);
            cp_async16(sB + doff, Bp + (size_t)(kk2 + k2) * N_S + s0 + m4);
        }
        asm volatile("cp.async.commit_group;\n" ::: "memory");
    };

    float acc[4][4][4];
#pragma unroll
    for (int mt = 0; mt < 4; mt++)
#pragma unroll
        for (int nt = 0; nt < 4; nt++)
#pragma unroll
            for (int q = 0; q < 4; q++) acc[mt][nt][q] = 0.0f;

    issue(0, 0);

    const int NSTAGE = (CC / 2) / BK2;   // 4
#pragma unroll
    for (int s = 0; s < NSTAGE; s++) {
        if (s + 1 < NSTAGE) {
            issue((s + 1) & 1, (s + 1) * BK2);
            asm volatile("cp.async.wait_group 1;\n" ::: "memory");
        } else {
            asm volatile("cp.async.wait_group 0;\n" ::: "memory");
        }
        __syncthreads();

        const uint32_t* Ab = &As2[s & 1][0];
        const uint32_t* Bb = &Bs2[s & 1][0];
#pragma unroll
        for (int kc2 = 0; kc2 < BK2; kc2 += 8) {
            uint32_t af[4][4], bfr[4][2];
#pragma unroll
            for (int mt = 0; mt < 4; mt++) {
                int m = warp_m + mt * 16 + g;
                af[mt][0] = Ab[(kc2 + tid4)     * SPITCH + m];
                af[mt][1] = Ab[(kc2 + tid4)     * SPITCH + m + 8];
                af[mt][2] = Ab[(kc2 + tid4 + 4) * SPITCH + m];
                af[mt][3] = Ab[(kc2 + tid4 + 4) * SPITCH + m + 8];
            }
#pragma unroll
            for (int nt = 0; nt < 4; nt++) {
                int nn = warp_n + nt * 8 + g;
                bfr[nt][0] = Bb[(kc2 + tid4)     * SPITCH + nn];
                bfr[nt][1] = Bb[(kc2 + tid4 + 4) * SPITCH + nn];
            }
#pragma unroll
            for (int mt = 0; mt < 4; mt++)
#pragma unroll
                for (int nt = 0; nt < 4; nt++) {
                    asm volatile(
                        "mma.sync.aligned.m16n8k16.row.col.f32.bf16.bf16.f32 "
                        "{%0,%1,%2,%3},{%4,%5,%6,%7},{%8,%9},{%0,%1,%2,%3};"
                        : "+f"(acc[mt][nt][0]), "+f"(acc[mt][nt][1]),
                          "+f"(acc[mt][nt][2]), "+f"(acc[mt][nt][3])
                        : "r"(af[mt][0]), "r"(af[mt][1]), "r"(af[mt][2]), "r"(af[mt][3]),
                          "r"(bfr[nt][0]), "r"(bfr[nt][1]));
                }
        }
        __syncthreads();
    }

    // Epilogue: f32 acc -> e4m3 pairs (2-byte stores)
    // c0:(row g, col 2t) c1:(g, 2t+1) c2:(g+8, 2t) c3:(g+8, 2t+1)
#pragma unroll
    for (int mt = 0; mt < 4; mt++) {
#pragma unroll
        for (int nt = 0; nt < 4; nt++) {
            int row = r0 + warp_m + mt * 16 + g;
            int col = s0 + warp_n + nt * 8 + 2 * tid4;
            uint16_t lo = f32x2_to_e4m3x2(acc[mt][nt][1], acc[mt][nt][0]);
            uint16_t hi = f32x2_to_e4m3x2(acc[mt][nt][3], acc[mt][nt][2]);
            *(uint16_t*)(Ct + (size_t)row * N_S + col)       = lo;
            *(uint16_t*)(Ct + (size_t)(row + 8) * N_S + col) = hi;
        }
    }
}

// ---------------------------------------------------------------------------
// Kernel 2: argmax over 126x126 candidates, fp8 T, packed f16x2 arithmetic.
// Block = 128 threads = 16 px (4x4 tile) x 8 subs; each thread owns 16 vs.
// Per us-step: 9 coalesced 16B loads (+2B tails), cvt e4m3->f16x2, sliding
// 3-window sums via byte_perm shifts, scalar f32 compare for argmax.
// ---------------------------------------------------------------------------
__device__ __forceinline__ uint32_t cvt_e4m3x2_f16x2(uint32_t s) {
    uint32_t r;
    asm("cvt.rn.f16x2.e4m3x2 %0, %1;" : "=r"(r) : "h"((uint16_t)s));
    return r;
}
__device__ __forceinline__ uint32_t hadd2u(uint32_t a, uint32_t b) {
    uint32_t r;
    asm("add.rn.f16x2 %0, %1, %2;" : "=r"(r) : "r"(a), "r"(b));
    return r;
}

__global__ __launch_bounds__(128) void argmax_kernel() {
    const int n   = blockIdx.z;
    const int tid = threadIdx.x;
    const int px  = tid >> 3;        // 0..15
    const int sub = tid & 7;         // 0..7
    const int di  = px >> 2;
    const int dj  = px & 3;
    const int i   = blockIdx.y * 4 + di;
    const int j   = blockIdx.x * 4 + dj;
    const int vs0 = sub << 4;        // 0..112

    float best = -FLT_MAX;
    int   bidx = 0;
    const bool valid = (i < HP) && (j < HP);

    if (valid) {
        const uint8_t* Tn = g_Tf8 + (size_t)n * M_R * N_S;
        const uint8_t* rp[3][3];
#pragma unroll
        for (int a = 0; a < 3; a++)
#pragma unroll
            for (int b = 0; b < 3; b++)
                rp[a][b] = Tn + (size_t)((i + a) * WW + (j + b)) * N_S + vs0;

        const bool has_tail = (sub < 7);   // sub==7: vs0=112, 16B reaches row end
        const int  pmax     = has_tail ? 8 : 7;

        for (int us = 0; us < USZ; us++) {
            uint32_t S[8];
#pragma unroll
            for (int p = 0; p < 8; p++) S[p] = 0;

#pragma unroll
            for (int a = 0; a < 3; a++) {
                const int off = (us + a) * WS;
#pragma unroll
                for (int b = 0; b < 3; b++) {
                    const uint8_t* p = rp[a][b] + off;
                    uint4 v = *(const uint4*)p;
                    uint32_t hh[9];
                    hh[0] = cvt_e4m3x2_f16x2(v.x & 0xffffu);
                    hh[1] = cvt_e4m3x2_f16x2(v.x >> 16);
                    hh[2] = cvt_e4m3x2_f16x2(v.y & 0xffffu);
                    hh[3] = cvt_e4m3x2_f16x2(v.y >> 16);
                    hh[4] = cvt_e4m3x2_f16x2(v.z & 0xffffu);
                    hh[5] = cvt_e4m3x2_f16x2(v.z >> 16);
                    hh[6] = cvt_e4m3x2_f16x2(v.w & 0xffffu);
                    hh[7] = cvt_e4m3x2_f16x2(v.w >> 16);
                    hh[8] = has_tail ? cvt_e4m3x2_f16x2(*(const uint16_t*)(p + 16))
                                     : 0u;
                    if (b == 0) {
#pragma unroll
                        for (int q = 0; q < 8; q++) S[q] = hadd2u(S[q], hh[q]);
                    } else if (b == 1) {
#pragma unroll
                        for (int q = 0; q < 8; q++)
                            S[q] = hadd2u(S[q], __byte_perm(hh[q], hh[q + 1], 0x5432));
                    } else {
#pragma unroll
                        for (int q = 0; q < 8; q++) S[q] = hadd2u(S[q], hh[q + 1]);
                    }
                }
            }

            const int ubase = us * USZ + vs0;
#pragma unroll
            for (int q = 0; q < 8; q++) {
                if (q < pmax) {
                    __half2 h = *(__half2*)&S[q];
                    float slo = __low2float(h);
                    float shi = __high2float(h);
                    if (slo > best) { best = slo; bidx = ubase + 2 * q; }
                    if (shi > best) { best = shi; bidx = ubase + 2 * q + 1; }
                }
            }
        }
    }

    // Reduce across the 8 subs of each pixel (8 consecutive lanes).
#pragma unroll
    for (int off = 4; off > 0; off >>= 1) {
        float ov = __shfl_xor_sync(0xffffffffu, best, off);
        int   oi = __shfl_xor_sync(0xffffffffu, bidx, off);
        if (ov > best || (ov == best && oi < bidx)) { best = ov; bidx = oi; }
    }
    if (valid && sub == 0)
        g_idx[(n * HP + i) * HP + j] = bidx;
}

// ---------------------------------------------------------------------------
// Kernel 3: gather matched color patch, L1 vs output patch, clip, global sum.
// 1024 threads per block for memory-level parallelism.
// ---------------------------------------------------------------------------
__global__ __launch_bounds__(1024) void l1_kernel(const float* __restrict__ outf,
                                                  const float* __restrict__ colf,
                                                  float* __restrict__ dout) {
    const int i = blockIdx.x;
    const int n = blockIdx.y;

    __shared__ float l1s[HP];
    __shared__ int   uu[HP];
    if (threadIdx.x < HP) {
        l1s[threadIdx.x] = 0.0f;
        uu[threadIdx.x]  = g_idx[(n * HP + i) * HP + threadIdx.x];
    }
    __syncthreads();

    for (int t = threadIdx.x; t < CC * HP; t += 1024) {
        int c = t / HP;
        int j = t - c * HP;
        int u  = uu[j];
        int us = u / USZ;
        int vs = u - us * USZ;

        const float* op = outf + ((size_t)(n * CC + c) * HH + i)  * WW + j;
        const float* cp = colf + ((size_t)(n * CC + c) * HS + us) * WS + vs;

        float s = 0.0f;
#pragma unroll
        for (int a = 0; a < 3; a++)
#pragma unroll
            for (int b = 0; b < 3; b++)
                s += fabsf(op[a * WW + b] - cp[a * WS + b]);
        atomicAdd(&l1s[j], s);
    }
    __syncthreads();

    if (threadIdx.x < HP) {
        float v = fminf(fmaxf(l1s[threadIdx.x], 0.0f), 1000.0f);
        atomicAdd(dout, v);
    }
}

// ---------------------------------------------------------------------------
// Launch
// Inputs (metadata order): 0 output_feat, 1 ref_feat, 2 shape_feat, 3 color_feat
// ---------------------------------------------------------------------------
extern "C" void kernel_launch(void* const* d_in, const int* in_sizes, int n_in,
                              void* d_out, int out_size) {
    const float* output_feat = (const float*)d_in[0];
    const float* ref_feat    = (const float*)d_in[1];
    const float* shape_feat  = (const float*)d_in[2];
    const float* color_feat  = (const float*)d_in[3];
    float* out = (float*)d_out;

    zero_kernel<<<1, 32>>>(out, out_size);

    pack_kernel<<<256, 256>>>(ref_feat,   g_Apk, M_R, NB * (CC / 2) * M_R);
    pack_kernel<<<512, 256>>>(shape_feat, g_Bpk, N_S, NB * (CC / 2) * N_S);

    dim3 g1(N_S / BN, M_R / BM, NB);            // 128 x 32 x 2
    gemm_kernel<<<g1, 256>>>();

    dim3 g2((HP + 3) / 4, (HP + 3) / 4, NB);    // 16 x 16 x 2
    argmax_kernel<<<g2, 128>>>();

    dim3 g3(HP, NB);                            // 62 x 2
    l1_kernel<<<g3, 1024>>>(output_feat, color_feat, out);
}

// round 6
// speedup vs baseline: 1.3627x; 1.3627x over previous
#include <cuda_runtime.h>
#include <cuda_bf16.h>
#include <cuda_fp16.h>
#include <math.h>
#include <float.h>
#include <stdint.h>

// Problem constants
#define NB   2
#define CC   128
#define HH   64
#define WW   64
#define HS   128
#define WS   128
#define HP   62          // HH - 2
#define USZ  126         // HS - 2
#define M_R  4096        // HH*WW   (ref pixels per image)
#define N_S  16384       // HS*WS   (shape pixels per image)

// Scratch
static __device__ __half   g_Th[(size_t)NB * M_R * N_S];         // 268 MB f16 Gram matrix
static __device__ uint32_t g_Apk[(size_t)NB * (CC/2) * M_R];     // 2 MB  bf162 k-pair packed ref
static __device__ uint32_t g_Bpk[(size_t)NB * (CC/2) * N_S];     // 8 MB  bf162 k-pair packed shape
static __device__ int      g_idx[NB * HP * HP];

// ---------------------------------------------------------------------------
// Kernel 0: zero the output scalar(s)
// ---------------------------------------------------------------------------
__global__ void zero_kernel(float* out, int n) {
    for (int i = threadIdx.x; i < n; i += blockDim.x) out[i] = 0.0f;
}

// ---------------------------------------------------------------------------
// Kernel 0b: pack fp32 [n][c][m] -> bf162 k-pair layout [n][k2][m]
// ---------------------------------------------------------------------------
__global__ void pack_kernel(const float* __restrict__ src, uint32_t* __restrict__ dst,
                            int M, int total) {
    for (int x = blockIdx.x * blockDim.x + threadIdx.x; x < total;
         x += gridDim.x * blockDim.x) {
        int m   = x % M;
        int nk2 = x / M;
        int n   = nk2 >> 6;       // /64
        int k2  = nk2 & 63;
        const float* s = src + ((size_t)(n * CC + 2 * k2)) * M + m;
        __nv_bfloat162 h = __floats2bfloat162_rn(s[0], s[M]);
        dst[x] = *(uint32_t*)&h;
    }
}

// ---------------------------------------------------------------------------
// Kernel 1: T[n,r,s] = sum_c ref[n,c,r] * shape[n,c,s]   (bf16 HMMA, f32 acc)
// Double-buffered cp.async, 128x128 tile; epilogue stores f16 via half2.
// ---------------------------------------------------------------------------
#define BM 128
#define BN 128
#define BK2 16          // k-pair rows per stage (BK = 32)
#define SPITCH 132      // padded row stride in u32

__device__ __forceinline__ void cp_async16(uint32_t smem_addr, const void* gptr) {
    asm volatile("cp.async.cg.shared.global [%0], [%1], 16;\n"
                 :: "r"(smem_addr), "l"(gptr));
}

__global__ __launch_bounds__(256) void gemm_kernel() {
    __shared__ __align__(16) uint32_t As2[2][BK2 * SPITCH];
    __shared__ __align__(16) uint32_t Bs2[2][BK2 * SPITCH];

    const int n = blockIdx.z;
    const uint32_t* Ap = g_Apk + (size_t)n * (CC / 2) * M_R;
    const uint32_t* Bp = g_Bpk + (size_t)n * (CC / 2) * N_S;
    __half*         Ct = g_Th  + (size_t)n * M_R * N_S;

    const int r0 = blockIdx.y * BM;
    const int s0 = blockIdx.x * BN;
    const int tid  = threadIdx.x;
    const int lane = tid & 31;
    const int wid  = tid >> 5;
    const int warp_m = (wid >> 2) * 64;
    const int warp_n = (wid & 3) * 32;
    const int g    = lane >> 2;
    const int tid4 = lane & 3;

    const uint32_t sA = (uint32_t)__cvta_generic_to_shared(&As2[0][0]);
    const uint32_t sB = (uint32_t)__cvta_generic_to_shared(&Bs2[0][0]);

    auto issue = [&](int buf, int kk2) {
#pragma unroll
        for (int h = 0; h < 2; h++) {
            int ch = tid + h * 256;
            int k2 = ch >> 5;
            int m4 = (ch & 31) << 2;
            uint32_t doff = (uint32_t)((buf * BK2 * SPITCH + k2 * SPITCH + m4) * 4);
            cp_async16(sA + doff, Ap + (size_t)(kk2 + k2) * M_R + r0 + m4);
            cp_async16(sB + doff, Bp + (size_t)(kk2 + k2) * N_S + s0 + m4);
        }
        asm volatile("cp.async.commit_group;\n" ::: "memory");
    };

    float acc[4][4][4];
#pragma unroll
    for (int mt = 0; mt < 4; mt++)
#pragma unroll
        for (int nt = 0; nt < 4; nt++)
#pragma unroll
            for (int q = 0; q < 4; q++) acc[mt][nt][q] = 0.0f;

    issue(0, 0);

    const int NSTAGE = (CC / 2) / BK2;   // 4
#pragma unroll
    for (int s = 0; s < NSTAGE; s++) {
        if (s + 1 < NSTAGE) {
            issue((s + 1) & 1, (s + 1) * BK2);
            asm volatile("cp.async.wait_group 1;\n" ::: "memory");
        } else {
            asm volatile("cp.async.wait_group 0;\n" ::: "memory");
        }
        __syncthreads();

        const uint32_t* Ab = &As2[s & 1][0];
        const uint32_t* Bb = &Bs2[s & 1][0];
#pragma unroll
        for (int kc2 = 0; kc2 < BK2; kc2 += 8) {
            uint32_t af[4][4], bfr[4][2];
#pragma unroll
            for (int mt = 0; mt < 4; mt++) {
                int m = warp_m + mt * 16 + g;
                af[mt][0] = Ab[(kc2 + tid4)     * SPITCH + m];
                af[mt][1] = Ab[(kc2 + tid4)     * SPITCH + m + 8];
                af[mt][2] = Ab[(kc2 + tid4 + 4) * SPITCH + m];
                af[mt][3] = Ab[(kc2 + tid4 + 4) * SPITCH + m + 8];
            }
#pragma unroll
            for (int nt = 0; nt < 4; nt++) {
                int nn = warp_n + nt * 8 + g;
                bfr[nt][0] = Bb[(kc2 + tid4)     * SPITCH + nn];
                bfr[nt][1] = Bb[(kc2 + tid4 + 4) * SPITCH + nn];
            }
#pragma unroll
            for (int mt = 0; mt < 4; mt++)
#pragma unroll
                for (int nt = 0; nt < 4; nt++) {
                    asm volatile(
                        "mma.sync.aligned.m16n8k16.row.col.f32.bf16.bf16.f32 "
                        "{%0,%1,%2,%3},{%4,%5,%6,%7},{%8,%9},{%0,%1,%2,%3};"
                        : "+f"(acc[mt][nt][0]), "+f"(acc[mt][nt][1]),
                          "+f"(acc[mt][nt][2]), "+f"(acc[mt][nt][3])
                        : "r"(af[mt][0]), "r"(af[mt][1]), "r"(af[mt][2]), "r"(af[mt][3]),
                          "r"(bfr[nt][0]), "r"(bfr[nt][1]));
                }
        }
        __syncthreads();
    }

    // Epilogue: f32 acc -> half2 stores (4B each, as in R3's best layout)
#pragma unroll
    for (int mt = 0; mt < 4; mt++) {
#pragma unroll
        for (int nt = 0; nt < 4; nt++) {
            int row = r0 + warp_m + mt * 16 + g;
            int col = s0 + warp_n + nt * 8 + 2 * tid4;
            __half2 lo = __floats2half2_rn(acc[mt][nt][0], acc[mt][nt][1]);
            __half2 hi = __floats2half2_rn(acc[mt][nt][2], acc[mt][nt][3]);
            *(__half2*)(Ct + (size_t)row * N_S + col)       = lo;
            *(__half2*)(Ct + (size_t)(row + 8) * N_S + col) = hi;
        }
    }
}

// ---------------------------------------------------------------------------
// Kernel 2: argmax, f16 T, packed half2 arithmetic, hierarchical max.
// 256 threads = 16 px (4x4 tile) x 16 subs; 8 vs per thread.
// Per us-step: 9 LDG.128 + <=9 LDG.32 tails, 36 HADD2 + 12 PRMT windows,
// 4-wide hmax tree + rare index-resolving scan.
// ---------------------------------------------------------------------------
__global__ __launch_bounds__(256) void argmax_kernel() {
    const int n   = blockIdx.z;
    const int tid = threadIdx.x;
    const int px  = tid >> 4;        // 0..15
    const int sub = tid & 15;        // 0..15
    const int di  = px >> 2;
    const int dj  = px & 3;
    const int i   = blockIdx.y * 4 + di;
    const int j   = blockIdx.x * 4 + dj;
    const int vs0 = sub << 3;        // 0..120

    const __half NEG_INF = __ushort_as_half((unsigned short)0xFC00);
    __half best_h = NEG_INF;
    int    bidx   = 0;
    const bool valid = (i < HP) && (j < HP);

    if (valid) {
        const __half* Tn = g_Th + (size_t)n * M_R * N_S;
        const __half* rp[3][3];
#pragma unroll
        for (int a = 0; a < 3; a++)
#pragma unroll
            for (int b = 0; b < 3; b++)
                rp[a][b] = Tn + (size_t)((i + a) * WW + (j + b)) * N_S + vs0;

        const bool tail = (sub == 15);   // vs0=120: 16B load already reaches row end
        const __half2 NEG2 = __halves2half2(NEG_INF, NEG_INF);

        for (int us = 0; us < USZ; us++) {
            __half2 S[4];
#pragma unroll
            for (int q = 0; q < 4; q++) S[q] = __float2half2_rn(0.0f);

#pragma unroll
            for (int a = 0; a < 3; a++) {
                const int off = (us + a) * WS;
#pragma unroll
                for (int b = 0; b < 3; b++) {
                    const __half* p = rp[a][b] + off;
                    uint4 v = *(const uint4*)p;
                    __half2 h0 = *(__half2*)&v.x;
                    __half2 h1 = *(__half2*)&v.y;
                    __half2 h2 = *(__half2*)&v.z;
                    __half2 h3 = *(__half2*)&v.w;
                    __half2 h4;
                    if (!tail) {
                        uint32_t t = *(const uint32_t*)(p + 8);
                        h4 = *(__half2*)&t;
                    } else {
                        h4 = __float2half2_rn(0.0f);
                    }
                    if (b == 0) {
                        S[0] = __hadd2(S[0], h0);
                        S[1] = __hadd2(S[1], h1);
                        S[2] = __hadd2(S[2], h2);
                        S[3] = __hadd2(S[3], h3);
                    } else if (b == 1) {
                        uint32_t u0 = *(uint32_t*)&h0, u1 = *(uint32_t*)&h1;
                        uint32_t u2 = *(uint32_t*)&h2, u3 = *(uint32_t*)&h3;
                        uint32_t u4 = *(uint32_t*)&h4;
                        uint32_t w0 = __byte_perm(u0, u1, 0x5432);
                        uint32_t w1 = __byte_perm(u1, u2, 0x5432);
                        uint32_t w2 = __byte_perm(u2, u3, 0x5432);
                        uint32_t w3 = __byte_perm(u3, u4, 0x5432);
                        S[0] = __hadd2(S[0], *(__half2*)&w0);
                        S[1] = __hadd2(S[1], *(__half2*)&w1);
                        S[2] = __hadd2(S[2], *(__half2*)&w2);
                        S[3] = __hadd2(S[3], *(__half2*)&w3);
                    } else {
                        S[0] = __hadd2(S[0], h1);
                        S[1] = __hadd2(S[1], h2);
                        S[2] = __hadd2(S[2], h3);
                        S[3] = __hadd2(S[3], h4);
                    }
                }
            }
            if (tail) S[3] = NEG2;   // vs 126,127 are invalid outputs

            // Hierarchical max over the 8 outputs of this step
            __half2 m01 = __hmax2(S[0], S[1]);
            __half2 m23 = __hmax2(S[2], S[3]);
            __half2 m   = __hmax2(m01, m23);
            __half  mh  = __hmax(__low2half(m), __high2half(m));

            if (__hgt(mh, best_h)) {
                best_h = mh;
                const int ubase = us * USZ + vs0;
                // find FIRST d with value == mh (guaranteed to exist)
                bool found = false;
#pragma unroll
                for (int q = 0; q < 4; q++) {
                    if (!found && __heq(__low2half(S[q]), mh))  { bidx = ubase + 2 * q;     found = true; }
                    if (!found && __heq(__high2half(S[q]), mh)) { bidx = ubase + 2 * q + 1; found = true; }
                }
            }
        }
    }

    // Reduce across the 16 subs of each pixel (16 consecutive lanes).
    float best = valid ? __half2float(best_h) : -FLT_MAX;
#pragma unroll
    for (int off = 8; off > 0; off >>= 1) {
        float ov = __shfl_xor_sync(0xffffffffu, best, off);
        int   oi = __shfl_xor_sync(0xffffffffu, bidx, off);
        if (ov > best || (ov == best && oi < bidx)) { best = ov; bidx = oi; }
    }
    if (valid && sub == 0)
        g_idx[(n * HP + i) * HP + j] = bidx;
}

// ---------------------------------------------------------------------------
// Kernel 3: gather matched color patch, L1 vs output patch, clip, global sum.
// ---------------------------------------------------------------------------
__global__ __launch_bounds__(1024) void l1_kernel(const float* __restrict__ outf,
                                                  const float* __restrict__ colf,
                                                  float* __restrict__ dout) {
    const int i = blockIdx.x;
    const int n = blockIdx.y;

    __shared__ float l1s[HP];
    __shared__ int   uu[HP];
    if (threadIdx.x < HP) {
        l1s[threadIdx.x] = 0.0f;
        uu[threadIdx.x]  = g_idx[(n * HP + i) * HP + threadIdx.x];
    }
    __syncthreads();

    for (int t = threadIdx.x; t < CC * HP; t += 1024) {
        int c = t / HP;
        int j = t - c * HP;
        int u  = uu[j];
        int us = u / USZ;
        int vs = u - us * USZ;

        const float* op = outf + ((size_t)(n * CC + c) * HH + i)  * WW + j;
        const float* cp = colf + ((size_t)(n * CC + c) * HS + us) * WS + vs;

        float s = 0.0f;
#pragma unroll
        for (int a = 0; a < 3; a++)
#pragma unroll
            for (int b = 0; b < 3; b++)
                s += fabsf(op[a * WW + b] - cp[a * WS + b]);
        atomicAdd(&l1s[j], s);
    }
    __syncthreads();

    if (threadIdx.x < HP) {
        float v = fminf(fmaxf(l1s[threadIdx.x], 0.0f), 1000.0f);
        atomicAdd(dout, v);
    }
}

// ---------------------------------------------------------------------------
// Launch
// Inputs (metadata order): 0 output_feat, 1 ref_feat, 2 shape_feat, 3 color_feat
// ---------------------------------------------------------------------------
extern "C" void kernel_launch(void* const* d_in, const int* in_sizes, int n_in,
                              void* d_out, int out_size) {
    const float* output_feat = (const float*)d_in[0];
    const float* ref_feat    = (const float*)d_in[1];
    const float* shape_feat  = (const float*)d_in[2];
    const float* color_feat  = (const float*)d_in[3];
    float* out = (float*)d_out;

    zero_kernel<<<1, 32>>>(out, out_size);

    pack_kernel<<<256, 256>>>(ref_feat,   g_Apk, M_R, NB * (CC / 2) * M_R);
    pack_kernel<<<512, 256>>>(shape_feat, g_Bpk, N_S, NB * (CC / 2) * N_S);

    dim3 g1(N_S / BN, M_R / BM, NB);            // 128 x 32 x 2
    gemm_kernel<<<g1, 256>>>();

    dim3 g2((HP + 3) / 4, (HP + 3) / 4, NB);    // 16 x 16 x 2
    argmax_kernel<<<g2, 256>>>();

    dim3 g3(HP, NB);                            // 62 x 2
    l1_kernel<<<g3, 1024>>>(output_feat, color_feat, out);
}

// round 7
// speedup vs baseline: 1.9009x; 1.3950x over previous
#include <cuda_runtime.h>
#include <cuda_bf16.h>
#include <cuda_fp16.h>
#include <math.h>
#include <float.h>
#include <stdint.h>

// Problem constants
#define NB   2
#define CC   128
#define HH   64
#define WW   64
#define HS   128
#define WS   128
#define HP   62          // HH - 2
#define USZ  126         // HS - 2
#define M_R  4096        // HH*WW   (ref pixels per image)
#define N_S  16384       // HS*WS   (shape pixels per image)

// Scratch
static __device__ __half   g_Th[(size_t)NB * M_R * N_S];         // 268 MB f16 Gram matrix
static __device__ uint32_t g_Apk[(size_t)NB * (CC/2) * M_R];     // 2 MB  bf162 k-pair packed ref
static __device__ uint32_t g_Bpk[(size_t)NB * (CC/2) * N_S];     // 8 MB  bf162 k-pair packed shape
static __device__ int      g_idx[NB * HP * HP];

__device__ __forceinline__ void cp_async16(uint32_t smem_addr, const void* gptr) {
    asm volatile("cp.async.cg.shared.global [%0], [%1], 16;\n"
                 :: "r"(smem_addr), "l"(gptr));
}

// ---------------------------------------------------------------------------
// Kernel 0: zero the output scalar(s)
// ---------------------------------------------------------------------------
__global__ void zero_kernel(float* out, int n) {
    for (int i = threadIdx.x; i < n; i += blockDim.x) out[i] = 0.0f;
}

// ---------------------------------------------------------------------------
// Kernel 0b: pack fp32 [n][c][m] -> bf162 k-pair layout [n][k2][m]
// ---------------------------------------------------------------------------
__global__ void pack_kernel(const float* __restrict__ src, uint32_t* __restrict__ dst,
                            int M, int total) {
    for (int x = blockIdx.x * blockDim.x + threadIdx.x; x < total;
         x += gridDim.x * blockDim.x) {
        int m   = x % M;
        int nk2 = x / M;
        int n   = nk2 >> 6;       // /64
        int k2  = nk2 & 63;
        const float* s = src + ((size_t)(n * CC + 2 * k2)) * M + m;
        __nv_bfloat162 h = __floats2bfloat162_rn(s[0], s[M]);
        dst[x] = *(uint32_t*)&h;
    }
}

// ---------------------------------------------------------------------------
// Kernel 1: T[n,r,s] = sum_c ref[n,c,r] * shape[n,c,s]   (bf16 HMMA, f32 acc)
// Double-buffered cp.async, 128x128 tile; epilogue stores f16 via half2.
// SPITCH=136 (mod 32 == 8): fragment-load banks = 8*tid4 + g -> conflict-free.
// ---------------------------------------------------------------------------
#define BM 128
#define BN 128
#define BK2 16          // k-pair rows per stage (BK = 32)
#define SPITCH 136      // padded row stride in u32

__global__ __launch_bounds__(256) void gemm_kernel() {
    __shared__ __align__(16) uint32_t As2[2][BK2 * SPITCH];
    __shared__ __align__(16) uint32_t Bs2[2][BK2 * SPITCH];

    const int n = blockIdx.z;
    const uint32_t* Ap = g_Apk + (size_t)n * (CC / 2) * M_R;
    const uint32_t* Bp = g_Bpk + (size_t)n * (CC / 2) * N_S;
    __half*         Ct = g_Th  + (size_t)n * M_R * N_S;

    const int r0 = blockIdx.y * BM;
    const int s0 = blockIdx.x * BN;
    const int tid  = threadIdx.x;
    const int lane = tid & 31;
    const int wid  = tid >> 5;
    const int warp_m = (wid >> 2) * 64;
    const int warp_n = (wid & 3) * 32;
    const int g    = lane >> 2;
    const int tid4 = lane & 3;

    const uint32_t sA = (uint32_t)__cvta_generic_to_shared(&As2[0][0]);
    const uint32_t sB = (uint32_t)__cvta_generic_to_shared(&Bs2[0][0]);

    auto issue = [&](int buf, int kk2) {
#pragma unroll
        for (int h = 0; h < 2; h++) {
            int ch = tid + h * 256;
            int k2 = ch >> 5;
            int m4 = (ch & 31) << 2;
            uint32_t doff = (uint32_t)((buf * BK2 * SPITCH + k2 * SPITCH + m4) * 4);
            cp_async16(sA + doff, Ap + (size_t)(kk2 + k2) * M_R + r0 + m4);
            cp_async16(sB + doff, Bp + (size_t)(kk2 + k2) * N_S + s0 + m4);
        }
        asm volatile("cp.async.commit_group;\n" ::: "memory");
    };

    float acc[4][4][4];
#pragma unroll
    for (int mt = 0; mt < 4; mt++)
#pragma unroll
        for (int nt = 0; nt < 4; nt++)
#pragma unroll
            for (int q = 0; q < 4; q++) acc[mt][nt][q] = 0.0f;

    issue(0, 0);

    const int NSTAGE = (CC / 2) / BK2;   // 4
#pragma unroll
    for (int s = 0; s < NSTAGE; s++) {
        if (s + 1 < NSTAGE) {
            issue((s + 1) & 1, (s + 1) * BK2);
            asm volatile("cp.async.wait_group 1;\n" ::: "memory");
        } else {
            asm volatile("cp.async.wait_group 0;\n" ::: "memory");
        }
        __syncthreads();

        const uint32_t* Ab = &As2[s & 1][0];
        const uint32_t* Bb = &Bs2[s & 1][0];
#pragma unroll
        for (int kc2 = 0; kc2 < BK2; kc2 += 8) {
            uint32_t af[4][4], bfr[4][2];
#pragma unroll
            for (int mt = 0; mt < 4; mt++) {
                int m = warp_m + mt * 16 + g;
                af[mt][0] = Ab[(kc2 + tid4)     * SPITCH + m];
                af[mt][1] = Ab[(kc2 + tid4)     * SPITCH + m + 8];
                af[mt][2] = Ab[(kc2 + tid4 + 4) * SPITCH + m];
                af[mt][3] = Ab[(kc2 + tid4 + 4) * SPITCH + m + 8];
            }
#pragma unroll
            for (int nt = 0; nt < 4; nt++) {
                int nn = warp_n + nt * 8 + g;
                bfr[nt][0] = Bb[(kc2 + tid4)     * SPITCH + nn];
                bfr[nt][1] = Bb[(kc2 + tid4 + 4) * SPITCH + nn];
            }
#pragma unroll
            for (int mt = 0; mt < 4; mt++)
#pragma unroll
                for (int nt = 0; nt < 4; nt++) {
                    asm volatile(
                        "mma.sync.aligned.m16n8k16.row.col.f32.bf16.bf16.f32 "
                        "{%0,%1,%2,%3},{%4,%5,%6,%7},{%8,%9},{%0,%1,%2,%3};"
                        : "+f"(acc[mt][nt][0]), "+f"(acc[mt][nt][1]),
                          "+f"(acc[mt][nt][2]), "+f"(acc[mt][nt][3])
                        : "r"(af[mt][0]), "r"(af[mt][1]), "r"(af[mt][2]), "r"(af[mt][3]),
                          "r"(bfr[nt][0]), "r"(bfr[nt][1]));
                }
        }
        __syncthreads();
    }

    // Epilogue: f32 acc -> half2 stores
#pragma unroll
    for (int mt = 0; mt < 4; mt++) {
#pragma unroll
        for (int nt = 0; nt < 4; nt++) {
            int row = r0 + warp_m + mt * 16 + g;
            int col = s0 + warp_n + nt * 8 + 2 * tid4;
            __half2 lo = __floats2half2_rn(acc[mt][nt][0], acc[mt][nt][1]);
            __half2 hi = __floats2half2_rn(acc[mt][nt][2], acc[mt][nt][3]);
            *(__half2*)(Ct + (size_t)row * N_S + col)       = lo;
            *(__half2*)(Ct + (size_t)(row + 8) * N_S + col) = hi;
        }
    }
}

// ---------------------------------------------------------------------------
// Kernel 2: argmax v3 — cp.async staged sliding window in smem.
// Block = 256 thr = 16 px (4x4) x 16 subs (8 vs each).
// Smem ring: 4 slots x 36 ref rows x 128 halves. Per us-step only the NEW
// shape row (9KB) is fetched from L2 (prefetched 4 steps ahead); all stencil
// reads come from smem. Tail halves via shfl_down of the neighbor's word.
// ---------------------------------------------------------------------------
__global__ __launch_bounds__(256) void argmax_kernel() {
    __shared__ __align__(16) __half buf[4][36][128];   // 36 KB

    const int n   = blockIdx.z;
    const int tid = threadIdx.x;
    const int px  = tid >> 4;        // 0..15
    const int sub = tid & 15;        // 0..15
    const int di  = px >> 2;
    const int dj  = px & 3;
    const int i0  = blockIdx.y * 4;
    const int j0  = blockIdx.x * 4;
    const int i   = i0 + di;
    const int j   = j0 + dj;
    const int vs0 = sub << 3;        // 0..120

    const __half* Tn = g_Th + (size_t)n * M_R * N_S;

    // stage loader: one shape row (srow) for all 36 ref rows -> one ring slot
    auto issue_srow = [&](int srow, int slot) {
#pragma unroll
        for (int it = 0; it < 3; it++) {
            int c = tid + it * 256;          // 0..767, need < 576
            if (c < 576) {
                int r36 = c >> 4;            // 0..35
                int seg = c & 15;            // 16B segment
                int t = r36 / 6, w = r36 - t * 6;
                int ri = min(i0 + t, HH - 1);
                int rj = min(j0 + w, WW - 1);
                const __half* src = Tn + (size_t)(ri * WW + rj) * N_S + srow * 128 + seg * 8;
                uint32_t daddr = (uint32_t)__cvta_generic_to_shared(&buf[slot][r36][seg * 8]);
                cp_async16(daddr, src);
            }
        }
        asm volatile("cp.async.commit_group;\n" ::: "memory");
    };

    // prologue: shape rows 0..3 into slots 0..3
    issue_srow(0, 0); issue_srow(1, 1); issue_srow(2, 2); issue_srow(3, 3);

    const __half NEG_INF = __ushort_as_half((unsigned short)0xFC00);
    const __half2 NEG2   = __halves2half2(NEG_INF, NEG_INF);
    __half best_h = NEG_INF;
    int    bidx   = 0;
    const bool tail  = (sub == 15);
    const bool valid = (i < HP) && (j < HP);

    for (int us = 0; us < USZ; us++) {
        if (us == USZ - 1) {
            asm volatile("cp.async.wait_group 0;\n" ::: "memory");
        } else {
            asm volatile("cp.async.wait_group 1;\n" ::: "memory");
        }
        __syncthreads();

        __half2 S[4];
#pragma unroll
        for (int q = 0; q < 4; q++) S[q] = __float2half2_rn(0.0f);

#pragma unroll
        for (int a = 0; a < 3; a++) {
            const __half* slotp = &buf[(us + a) & 3][0][0];
#pragma unroll
            for (int b = 0; b < 3; b++) {
                const __half* p = slotp + ((di + a) * 6 + (dj + b)) * 128 + vs0;
                uint4 v = *(const uint4*)p;
                // tail halves (vs0+8, vs0+9) = neighbor sub's first word
                uint32_t u4 = __shfl_down_sync(0xffffffffu, v.x, 1);
                __half2 h0 = *(__half2*)&v.x;
                __half2 h1 = *(__half2*)&v.y;
                __half2 h2 = *(__half2*)&v.z;
                __half2 h3 = *(__half2*)&v.w;
                __half2 h4 = *(__half2*)&u4;
                if (b == 0) {
                    S[0] = __hadd2(S[0], h0);
                    S[1] = __hadd2(S[1], h1);
                    S[2] = __hadd2(S[2], h2);
                    S[3] = __hadd2(S[3], h3);
                } else if (b == 1) {
                    uint32_t u0 = *(uint32_t*)&h0, u1 = *(uint32_t*)&h1;
                    uint32_t u2 = *(uint32_t*)&h2, u3 = *(uint32_t*)&h3;
                    uint32_t w0 = __byte_perm(u0, u1, 0x5432);
                    uint32_t w1 = __byte_perm(u1, u2, 0x5432);
                    uint32_t w2 = __byte_perm(u2, u3, 0x5432);
                    uint32_t w3 = __byte_perm(u3, u4, 0x5432);
                    S[0] = __hadd2(S[0], *(__half2*)&w0);
                    S[1] = __hadd2(S[1], *(__half2*)&w1);
                    S[2] = __hadd2(S[2], *(__half2*)&w2);
                    S[3] = __hadd2(S[3], *(__half2*)&w3);
                } else {
                    S[0] = __hadd2(S[0], h1);
                    S[1] = __hadd2(S[1], h2);
                    S[2] = __hadd2(S[2], h3);
                    S[3] = __hadd2(S[3], h4);
                }
            }
        }
        if (tail) S[3] = NEG2;   // vs 126,127 invalid (also masks cross-pixel shfl)

        // hierarchical max over this step's 8 outputs
        __half2 m01 = __hmax2(S[0], S[1]);
        __half2 m23 = __hmax2(S[2], S[3]);
        __half2 m   = __hmax2(m01, m23);
        __half  mh  = __hmax(__low2half(m), __high2half(m));

        if (__hgt(mh, best_h)) {
            best_h = mh;
            const int ubase = us * USZ + vs0;
            bool found = false;
#pragma unroll
            for (int q = 0; q < 4; q++) {
                if (!found && __heq(__low2half(S[q]), mh))  { bidx = ubase + 2 * q;     found = true; }
                if (!found && __heq(__high2half(S[q]), mh)) { bidx = ubase + 2 * q + 1; found = true; }
            }
        }

        __syncthreads();
        if (us + 4 <= HS - 1) issue_srow(us + 4, (us + 4) & 3);
    }

    // Reduce across the 16 subs of each pixel (16 consecutive lanes).
    float best = valid ? __half2float(best_h) : -FLT_MAX;
#pragma unroll
    for (int off = 8; off > 0; off >>= 1) {
        float ov = __shfl_xor_sync(0xffffffffu, best, off);
        int   oi = __shfl_xor_sync(0xffffffffu, bidx, off);
        if (ov > best || (ov == best && oi < bidx)) { best = ov; bidx = oi; }
    }
    if (valid && sub == 0)
        g_idx[(n * HP + i) * HP + j] = bidx;
}

// ---------------------------------------------------------------------------
// Kernel 3: gather matched color patch, L1 vs output patch, clip, global sum.
// ---------------------------------------------------------------------------
__global__ __launch_bounds__(1024) void l1_kernel(const float* __restrict__ outf,
                                                  const float* __restrict__ colf,
                                                  float* __restrict__ dout) {
    const int i = blockIdx.x;
    const int n = blockIdx.y;

    __shared__ float l1s[HP];
    __shared__ int   uu[HP];
    if (threadIdx.x < HP) {
        l1s[threadIdx.x] = 0.0f;
        uu[threadIdx.x]  = g_idx[(n * HP + i) * HP + threadIdx.x];
    }
    __syncthreads();

    for (int t = threadIdx.x; t < CC * HP; t += 1024) {
        int c = t / HP;
        int j = t - c * HP;
        int u  = uu[j];
        int us = u / USZ;
        int vs = u - us * USZ;

        const float* op = outf + ((size_t)(n * CC + c) * HH + i)  * WW + j;
        const float* cp = colf + ((size_t)(n * CC + c) * HS + us) * WS + vs;

        float s = 0.0f;
#pragma unroll
        for (int a = 0; a < 3; a++)
#pragma unroll
            for (int b = 0; b < 3; b++)
                s += fabsf(op[a * WW + b] - cp[a * WS + b]);
        atomicAdd(&l1s[j], s);
    }
    __syncthreads();

    if (threadIdx.x < HP) {
        float v = fminf(fmaxf(l1s[threadIdx.x], 0.0f), 1000.0f);
        atomicAdd(dout, v);
    }
}

// ---------------------------------------------------------------------------
// Launch
// Inputs (metadata order): 0 output_feat, 1 ref_feat, 2 shape_feat, 3 color_feat
// ---------------------------------------------------------------------------
extern "C" void kernel_launch(void* const* d_in, const int* in_sizes, int n_in,
                              void* d_out, int out_size) {
    const float* output_feat = (const float*)d_in[0];
    const float* ref_feat    = (const float*)d_in[1];
    const float* shape_feat  = (const float*)d_in[2];
    const float* color_feat  = (const float*)d_in[3];
    float* out = (float*)d_out;

    zero_kernel<<<1, 32>>>(out, out_size);

    pack_kernel<<<256, 256>>>(ref_feat,   g_Apk, M_R, NB * (CC / 2) * M_R);
    pack_kernel<<<512, 256>>>(shape_feat, g_Bpk, N_S, NB * (CC / 2) * N_S);

    dim3 g1(N_S / BN, M_R / BM, NB);            // 128 x 32 x 2
    gemm_kernel<<<g1, 256>>>();

    dim3 g2(16, 16, NB);                        // 4x4 px per block
    argmax_kernel<<<g2, 256>>>();

    dim3 g3(HP, NB);                            // 62 x 2
    l1_kernel<<<g3, 1024>>>(output_feat, color_feat, out);
}

// round 8
// speedup vs baseline: 2.0366x; 1.0714x over previous
#include <cuda_runtime.h>
#include <cuda_bf16.h>
#include <cuda_fp16.h>
#include <math.h>
#include <float.h>
#include <stdint.h>

// Problem constants
#define NB   2
#define CC   128
#define HH   64
#define WW   64
#define HS   128
#define WS   128
#define HP   62          // HH - 2
#define USZ  126         // HS - 2
#define M_R  4096        // HH*WW   (ref pixels per image)
#define N_S  16384       // HS*WS   (shape pixels per image)

// Scratch
static __device__ __half   g_Th[(size_t)NB * M_R * N_S];         // 268 MB f16 Gram matrix
static __device__ uint32_t g_Apk[(size_t)NB * (CC/2) * M_R];     // 2 MB  bf162 k-pair packed ref
static __device__ uint32_t g_Bpk[(size_t)NB * (CC/2) * N_S];     // 8 MB  bf162 k-pair packed shape
static __device__ unsigned long long g_pack[NB * HP * HP];       // packed (key|~idx) argmax

__device__ __forceinline__ void cp_async16(uint32_t smem_addr, const void* gptr) {
    asm volatile("cp.async.cg.shared.global [%0], [%1], 16;\n"
                 :: "r"(smem_addr), "l"(gptr));
}

// ---------------------------------------------------------------------------
// Kernel 0: zero output scalar(s) + packed argmax array
// ---------------------------------------------------------------------------
__global__ void zero_kernel(float* out, int n) {
    int t = blockIdx.x * blockDim.x + threadIdx.x;
    if (t < n) out[t] = 0.0f;
    for (int x = t; x < NB * HP * HP; x += gridDim.x * blockDim.x)
        g_pack[x] = 0ull;
}

// ---------------------------------------------------------------------------
// Kernel 0b: pack fp32 [n][c][m] -> bf162 k-pair layout [n][k2][m]
// ---------------------------------------------------------------------------
__global__ void pack_kernel(const float* __restrict__ src, uint32_t* __restrict__ dst,
                            int M, int total) {
    for (int x = blockIdx.x * blockDim.x + threadIdx.x; x < total;
         x += gridDim.x * blockDim.x) {
        int m   = x % M;
        int nk2 = x / M;
        int n   = nk2 >> 6;       // /64
        int k2  = nk2 & 63;
        const float* s = src + ((size_t)(n * CC + 2 * k2)) * M + m;
        __nv_bfloat162 h = __floats2bfloat162_rn(s[0], s[M]);
        dst[x] = *(uint32_t*)&h;
    }
}

// ---------------------------------------------------------------------------
// Kernel 1: T[n,r,s] = sum_c ref[n,c,r] * shape[n,c,s]   (bf16 HMMA, f32 acc)
// Double-buffered cp.async, 128x128 tile, SPITCH=136 (conflict-free frags).
// Epilogue staged through smem -> STG.128 coalesced stores.
// ---------------------------------------------------------------------------
#define BM 128
#define BN 128
#define BK2 16          // k-pair rows per stage (BK = 32)
#define SPITCH 136      // padded row stride in u32
#define CPITCH 136      // epilogue staging pitch in halves

__global__ __launch_bounds__(256) void gemm_kernel() {
    __shared__ __align__(16) uint32_t As2[2][BK2 * SPITCH];
    __shared__ __align__(16) uint32_t Bs2[2][BK2 * SPITCH];

    const int n = blockIdx.z;
    const uint32_t* Ap = g_Apk + (size_t)n * (CC / 2) * M_R;
    const uint32_t* Bp = g_Bpk + (size_t)n * (CC / 2) * N_S;
    __half*         Ct = g_Th  + (size_t)n * M_R * N_S;

    const int r0 = blockIdx.y * BM;
    const int s0 = blockIdx.x * BN;
    const int tid  = threadIdx.x;
    const int lane = tid & 31;
    const int wid  = tid >> 5;
    const int wg   = wid >> 2;            // m-warp group 0/1
    const int warp_m = wg * 64;
    const int warp_n = (wid & 3) * 32;
    const int g    = lane >> 2;
    const int tid4 = lane & 3;

    const uint32_t sA = (uint32_t)__cvta_generic_to_shared(&As2[0][0]);
    const uint32_t sB = (uint32_t)__cvta_generic_to_shared(&Bs2[0][0]);

    auto issue = [&](int buf, int kk2) {
#pragma unroll
        for (int h = 0; h < 2; h++) {
            int ch = tid + h * 256;
            int k2 = ch >> 5;
            int m4 = (ch & 31) << 2;
            uint32_t doff = (uint32_t)((buf * BK2 * SPITCH + k2 * SPITCH + m4) * 4);
            cp_async16(sA + doff, Ap + (size_t)(kk2 + k2) * M_R + r0 + m4);
            cp_async16(sB + doff, Bp + (size_t)(kk2 + k2) * N_S + s0 + m4);
        }
        asm volatile("cp.async.commit_group;\n" ::: "memory");
    };

    float acc[4][4][4];
#pragma unroll
    for (int mt = 0; mt < 4; mt++)
#pragma unroll
        for (int nt = 0; nt < 4; nt++)
#pragma unroll
            for (int q = 0; q < 4; q++) acc[mt][nt][q] = 0.0f;

    issue(0, 0);

    const int NSTAGE = (CC / 2) / BK2;   // 4
#pragma unroll
    for (int s = 0; s < NSTAGE; s++) {
        if (s + 1 < NSTAGE) {
            issue((s + 1) & 1, (s + 1) * BK2);
            asm volatile("cp.async.wait_group 1;\n" ::: "memory");
        } else {
            asm volatile("cp.async.wait_group 0;\n" ::: "memory");
        }
        __syncthreads();

        const uint32_t* Ab = &As2[s & 1][0];
        const uint32_t* Bb = &Bs2[s & 1][0];
#pragma unroll
        for (int kc2 = 0; kc2 < BK2; kc2 += 8) {
            uint32_t af[4][4], bfr[4][2];
#pragma unroll
            for (int mt = 0; mt < 4; mt++) {
                int m = warp_m + mt * 16 + g;
                af[mt][0] = Ab[(kc2 + tid4)     * SPITCH + m];
                af[mt][1] = Ab[(kc2 + tid4)     * SPITCH + m + 8];
                af[mt][2] = Ab[(kc2 + tid4 + 4) * SPITCH + m];
                af[mt][3] = Ab[(kc2 + tid4 + 4) * SPITCH + m + 8];
            }
#pragma unroll
            for (int nt = 0; nt < 4; nt++) {
                int nn = warp_n + nt * 8 + g;
                bfr[nt][0] = Bb[(kc2 + tid4)     * SPITCH + nn];
                bfr[nt][1] = Bb[(kc2 + tid4 + 4) * SPITCH + nn];
            }
#pragma unroll
            for (int mt = 0; mt < 4; mt++)
#pragma unroll
                for (int nt = 0; nt < 4; nt++) {
                    asm volatile(
                        "mma.sync.aligned.m16n8k16.row.col.f32.bf16.bf16.f32 "
                        "{%0,%1,%2,%3},{%4,%5,%6,%7},{%8,%9},{%0,%1,%2,%3};"
                        : "+f"(acc[mt][nt][0]), "+f"(acc[mt][nt][1]),
                          "+f"(acc[mt][nt][2]), "+f"(acc[mt][nt][3])
                        : "r"(af[mt][0]), "r"(af[mt][1]), "r"(af[mt][2]), "r"(af[mt][3]),
                          "r"(bfr[nt][0]), "r"(bfr[nt][1]));
                }
        }
        __syncthreads();
    }

    // ---- Epilogue: stage each 32-row chunk through smem, store STG.128 ----
    __half* Cs = (__half*)&As2[0][0];   // 32 * CPITCH halves = 8704 B
#pragma unroll
    for (int mt = 0; mt < 4; mt++) {
        __syncthreads();
        const int rl0 = wg * 16 + g;      // 0..15 | 16..31
#pragma unroll
        for (int nt = 0; nt < 4; nt++) {
            int col = warp_n + nt * 8 + 2 * tid4;
            *(__half2*)&Cs[rl0 * CPITCH + col] =
                __floats2half2_rn(acc[mt][nt][0], acc[mt][nt][1]);
            *(__half2*)&Cs[(rl0 + 8) * CPITCH + col] =
                __floats2half2_rn(acc[mt][nt][2], acc[mt][nt][3]);
        }
        __syncthreads();
#pragma unroll
        for (int h = 0; h < 2; h++) {
            int c = tid + h * 256;        // 0..511
            int rl = c >> 4;              // 0..31
            int seg = c & 15;
            uint4 v = *(uint4*)&Cs[rl * CPITCH + seg * 8];
            int grow = r0 + mt * 16 + ((rl >> 4) ? 64 : 0) + (rl & 15);
            *(uint4*)(Ct + (size_t)grow * N_S + s0 + seg * 8) = v;
        }
    }
}

// ---------------------------------------------------------------------------
// Kernel 2: argmax v4 — ring-5 smem, 1 barrier/step, us-split x2, u64 atomic.
// Block = 256 thr = 16 px (4x4) x 16 subs (8 vs each); 63 steps per block.
// ---------------------------------------------------------------------------
__global__ __launch_bounds__(256) void argmax_kernel() {
    __shared__ __align__(16) __half buf[5][36][128];   // 45 KB

    const int n    = blockIdx.z & 1;
    const int part = blockIdx.z >> 1;     // 0 or 1
    const int base = part * 63;           // us range [base, base+63)
    const int tid = threadIdx.x;
    const int px  = tid >> 4;
    const int sub = tid & 15;
    const int di  = px >> 2;
    const int dj  = px & 3;
    const int i0  = blockIdx.y * 4;
    const int j0  = blockIdx.x * 4;
    const int i   = i0 + di;
    const int j   = j0 + dj;
    const int vs0 = sub << 3;

    const __half* Tn = g_Th + (size_t)n * M_R * N_S;

    // load global shape row (base+lr) into ring slot
    auto issue_srow = [&](int lr, int slot) {
        int srow = base + lr;
#pragma unroll
        for (int it = 0; it < 3; it++) {
            int c = tid + it * 256;
            if (c < 576) {
                int r36 = c >> 4;
                int seg = c & 15;
                int t = r36 / 6, w = r36 - t * 6;
                int ri = min(i0 + t, HH - 1);
                int rj = min(j0 + w, WW - 1);
                const __half* src = Tn + (size_t)(ri * WW + rj) * N_S + srow * 128 + seg * 8;
                uint32_t daddr = (uint32_t)__cvta_generic_to_shared(&buf[slot][r36][seg * 8]);
                cp_async16(daddr, src);
            }
        }
        asm volatile("cp.async.commit_group;\n" ::: "memory");
    };

    issue_srow(0, 0); issue_srow(1, 1); issue_srow(2, 2); issue_srow(3, 3);

    const __half NEG_INF = __ushort_as_half((unsigned short)0xFC00);
    const __half2 NEG2   = __halves2half2(NEG_INF, NEG_INF);
    __half best_h = NEG_INF;
    int    bidx   = 0;
    const bool tail  = (sub == 15);
    const bool valid = (i < HP) && (j < HP);

    int s0 = 0;   // ring slot of row k
    for (int k = 0; k < 63; k++) {
        if (k == 62) {
            asm volatile("cp.async.wait_group 0;\n" ::: "memory");
        } else {
            asm volatile("cp.async.wait_group 1;\n" ::: "memory");
        }
        __syncthreads();

        int s1 = s0 + 1; if (s1 == 5) s1 = 0;
        int s2 = s1 + 1; if (s2 == 5) s2 = 0;
        const __half* sp[3] = { &buf[s0][0][0], &buf[s1][0][0], &buf[s2][0][0] };

        __half2 S[4];
#pragma unroll
        for (int q = 0; q < 4; q++) S[q] = __float2half2_rn(0.0f);

#pragma unroll
        for (int a = 0; a < 3; a++) {
            const __half* slotp = sp[a];
#pragma unroll
            for (int b = 0; b < 3; b++) {
                const __half* p = slotp + ((di + a) * 6 + (dj + b)) * 128 + vs0;
                uint4 v = *(const uint4*)p;
                uint32_t u4 = __shfl_down_sync(0xffffffffu, v.x, 1);
                __half2 h0 = *(__half2*)&v.x;
                __half2 h1 = *(__half2*)&v.y;
                __half2 h2 = *(__half2*)&v.z;
                __half2 h3 = *(__half2*)&v.w;
                __half2 h4 = *(__half2*)&u4;
                if (b == 0) {
                    S[0] = __hadd2(S[0], h0);
                    S[1] = __hadd2(S[1], h1);
                    S[2] = __hadd2(S[2], h2);
                    S[3] = __hadd2(S[3], h3);
                } else if (b == 1) {
                    uint32_t u0 = *(uint32_t*)&h0, u1 = *(uint32_t*)&h1;
                    uint32_t u2 = *(uint32_t*)&h2, u3 = *(uint32_t*)&h3;
                    uint32_t w0 = __byte_perm(u0, u1, 0x5432);
                    uint32_t w1 = __byte_perm(u1, u2, 0x5432);
                    uint32_t w2 = __byte_perm(u2, u3, 0x5432);
                    uint32_t w3 = __byte_perm(u3, u4, 0x5432);
                    S[0] = __hadd2(S[0], *(__half2*)&w0);
                    S[1] = __hadd2(S[1], *(__half2*)&w1);
                    S[2] = __hadd2(S[2], *(__half2*)&w2);
                    S[3] = __hadd2(S[3], *(__half2*)&w3);
                } else {
                    S[0] = __hadd2(S[0], h1);
                    S[1] = __hadd2(S[1], h2);
                    S[2] = __hadd2(S[2], h3);
                    S[3] = __hadd2(S[3], h4);
                }
            }
        }
        if (tail) S[3] = NEG2;

        __half2 m01 = __hmax2(S[0], S[1]);
        __half2 m23 = __hmax2(S[2], S[3]);
        __half2 m   = __hmax2(m01, m23);
        __half  mh  = __hmax(__low2half(m), __high2half(m));

        if (__hgt(mh, best_h)) {
            best_h = mh;
            const int ubase = (base + k) * USZ + vs0;
            bool found = false;
#pragma unroll
            for (int q = 0; q < 4; q++) {
                if (!found && __heq(__low2half(S[q]), mh))  { bidx = ubase + 2 * q;     found = true; }
                if (!found && __heq(__high2half(S[q]), mh)) { bidx = ubase + 2 * q + 1; found = true; }
            }
        }

        // prefetch row k+4 into slot (s0+4)%5 = (s0-1)%5 — its old row (k-1)
        // was last read at step k-1, ordered by this step's entry barrier.
        if (k <= 60) {
            int sw = (s0 == 0) ? 4 : s0 - 1;
            issue_srow(k + 4, sw);
        }
        s0 = s1;
    }

    // per-pixel reduce over the 16 subs (16 consecutive lanes)
    float best = valid ? __half2float(best_h) : -FLT_MAX;
#pragma unroll
    for (int off = 8; off > 0; off >>= 1) {
        float ov = __shfl_xor_sync(0xffffffffu, best, off);
        int   oi = __shfl_xor_sync(0xffffffffu, bidx, off);
        if (ov > best || (ov == best && oi < bidx)) { best = ov; bidx = oi; }
    }
    if (valid && sub == 0) {
        uint32_t fb  = __float_as_uint(best);
        uint32_t key = ((int)fb < 0) ? ~fb : (fb | 0x80000000u);
        unsigned long long pk =
            ((unsigned long long)key << 32) | (uint32_t)(0xFFFFFFFFu - (uint32_t)bidx);
        atomicMax(&g_pack[(n * HP + i) * HP + j], pk);
    }
}

// ---------------------------------------------------------------------------
// Kernel 3: gather matched color patch, L1 vs output patch, clip, global sum.
// ---------------------------------------------------------------------------
__global__ __launch_bounds__(1024) void l1_kernel(const float* __restrict__ outf,
                                                  const float* __restrict__ colf,
                                                  float* __restrict__ dout) {
    const int i = blockIdx.x;
    const int n = blockIdx.y;

    __shared__ float l1s[HP];
    __shared__ int   uu[HP];
    if (threadIdx.x < HP) {
        l1s[threadIdx.x] = 0.0f;
        unsigned long long pk = g_pack[(n * HP + i) * HP + threadIdx.x];
        uu[threadIdx.x] = (int)(0xFFFFFFFFu - (uint32_t)(pk & 0xFFFFFFFFull));
    }
    __syncthreads();

    for (int t = threadIdx.x; t < CC * HP; t += 1024) {
        int c = t / HP;
        int j = t - c * HP;
        int u  = uu[j];
        int us = u / USZ;
        int vs = u - us * USZ;

        const float* op = outf + ((size_t)(n * CC + c) * HH + i)  * WW + j;
        const float* cp = colf + ((size_t)(n * CC + c) * HS + us) * WS + vs;

        float s = 0.0f;
#pragma unroll
        for (int a = 0; a < 3; a++)
#pragma unroll
            for (int b = 0; b < 3; b++)
                s += fabsf(op[a * WW + b] - cp[a * WS + b]);
        atomicAdd(&l1s[j], s);
    }
    __syncthreads();

    if (threadIdx.x < HP) {
        float v = fminf(fmaxf(l1s[threadIdx.x], 0.0f), 1000.0f);
        atomicAdd(dout, v);
    }
}

// ---------------------------------------------------------------------------
// Launch
// Inputs (metadata order): 0 output_feat, 1 ref_feat, 2 shape_feat, 3 color_feat
// ---------------------------------------------------------------------------
extern "C" void kernel_launch(void* const* d_in, const int* in_sizes, int n_in,
                              void* d_out, int out_size) {
    const float* output_feat = (const float*)d_in[0];
    const float* ref_feat    = (const float*)d_in[1];
    const float* shape_feat  = (const float*)d_in[2];
    const float* color_feat  = (const float*)d_in[3];
    float* out = (float*)d_out;

    zero_kernel<<<32, 256>>>(out, out_size);

    pack_kernel<<<256, 256>>>(ref_feat,   g_Apk, M_R, NB * (CC / 2) * M_R);
    pack_kernel<<<512, 256>>>(shape_feat, g_Bpk, N_S, NB * (CC / 2) * N_S);

    dim3 g1(N_S / BN, M_R / BM, NB);            // 128 x 32 x 2
    gemm_kernel<<<g1, 256>>>();

    dim3 g2(16, 16, NB * 2);                    // 4x4 px per block, us-split x2
    argmax_kernel<<<g2, 256>>>();

    dim3 g3(HP, NB);                            // 62 x 2
    l1_kernel<<<g3, 1024>>>(output_feat, color_feat, out);
}